// round 6
// baseline (speedup 1.0000x reference)
#include <cuda_runtime.h>
#include <cuda_bf16.h>
#include <cstdint>

#define BATCH   2048
#define IN_DIM  512
#define HID     1024
#define NEXP    16
#define EPSBN   1e-5f

// 4-stage pipeline, K-chunk 32.
// stage layout: Ahi 8K | Alo 8K | Bhi 4K | Blo 4K = 24KB; 4 stages = 96KB.
#define STAGE_BYTES 24576
#define NSTAGE      4
#define SMEM_TOTAL  (NSTAGE * STAGE_BYTES)
#define NITER       256           /* 16 experts x 16 k-chunks of 32 */

// ---------------- scratch (device globals) -----------------------------------
__device__ __align__(1024) __nv_bfloat16 g_xg_hi[BATCH * IN_DIM];
__device__ __align__(1024) __nv_bfloat16 g_xg_lo[BATCH * IN_DIM];
__device__ __align__(1024) __nv_bfloat16 g_Whi[NEXP * IN_DIM * HID];   // [e][k][n]
__device__ __align__(1024) __nv_bfloat16 g_Wlo[NEXP * IN_DIM * HID];
__device__ float g_gate[BATCH * NEXP];
__device__ float g_scale[NEXP * HID];
__device__ float g_shift[NEXP * HID];

// int32/int64-agnostic expert index decode (validated round 2)
__device__ __forceinline__ int load_expert_idx(const void* p, int e) {
    const int* v = (const int*)p;
    bool is64 = ((v[1] | v[3] | v[5] | v[7]) == 0);
    return (is64 ? v[2 * e] : v[e]) & (NEXP - 1);
}

// ---------------- K1: LoRA sigmoid gate + softmax gate (proven) -------------
__global__ void __launch_bounds__(128) prep_xg_gate(
    const float* __restrict__ x, const float* __restrict__ gs_in,
    const float* __restrict__ gate_w, const float* __restrict__ lora_A,
    const float* __restrict__ lora_B)
{
    int row = blockIdx.x, tid = threadIdx.x, lane = tid & 31, wid = tid >> 5;
    __shared__ float xs[IN_DIM], gss[IN_DIM], w0s[4], w1s[4], pesh[4][16];
    for (int i = tid; i < IN_DIM; i += 128) {
        xs[i]  = x[row * IN_DIM + i];
        gss[i] = gs_in[row * IN_DIM + i];
    }
    __syncthreads();
    float p0 = 0.f, p1 = 0.f;
    for (int i = tid; i < IN_DIM; i += 128) {
        float v = xs[i];
        p0 = fmaf(v, lora_A[i * 2 + 0], p0);
        p1 = fmaf(v, lora_A[i * 2 + 1], p1);
    }
#pragma unroll
    for (int o = 16; o > 0; o >>= 1) {
        p0 += __shfl_xor_sync(~0u, p0, o);
        p1 += __shfl_xor_sync(~0u, p1, o);
    }
    if (lane == 0) { w0s[wid] = p0; w1s[wid] = p1; }
    float pe[16];
#pragma unroll
    for (int e = 0; e < 16; e++) pe[e] = 0.f;
    for (int i = tid; i < IN_DIM; i += 128) {
        float v = gss[i];
#pragma unroll
        for (int e = 0; e < 16; e++) pe[e] = fmaf(v, gate_w[i * 16 + e], pe[e]);
    }
#pragma unroll
    for (int o = 16; o > 0; o >>= 1)
#pragma unroll
        for (int e = 0; e < 16; e++) pe[e] += __shfl_xor_sync(~0u, pe[e], o);
    if (lane == 0)
#pragma unroll
        for (int e = 0; e < 16; e++) pesh[wid][e] = pe[e];
    __syncthreads();
    if (tid < 16) {
        float l = pesh[0][tid] + pesh[1][tid] + pesh[2][tid] + pesh[3][tid], m = l;
#pragma unroll
        for (int o = 8; o > 0; o >>= 1) m = fmaxf(m, __shfl_xor_sync(0xffffu, m, o));
        float ex = __expf(l - m), s = ex;
#pragma unroll
        for (int o = 8; o > 0; o >>= 1) s += __shfl_xor_sync(0xffffu, s, o);
        g_gate[row * 16 + tid] = ex / s;
    }
    float t0 = w0s[0] + w0s[1] + w0s[2] + w0s[3];
    float t1 = w1s[0] + w1s[1] + w1s[2] + w1s[3];
    for (int i = tid; i < IN_DIM; i += 128) {
        float z = fmaf(t0, lora_B[i], t1 * lora_B[IN_DIM + i]);
        float v = xs[i] / (1.f + __expf(-z));
        __nv_bfloat16 hi = __float2bfloat16(v);
        g_xg_hi[row * IN_DIM + i] = hi;
        g_xg_lo[row * IN_DIM + i] = __float2bfloat16(v - __bfloat162float(hi));
    }
}

// ---------------- K2: gather + split W (layout [e][k][n], proven) -----------
__global__ void __launch_bounds__(256) prep_W(
    const void* __restrict__ eidx, const float* __restrict__ ew)
{
    int i   = blockIdx.x * 256 + threadIdx.x;
    int e   = i >> 19;
    int rem = i & ((1 << 19) - 1);
    int se  = load_expert_idx(eidx, e);
    float w = ew[(size_t)se * (IN_DIM * HID) + rem];
    __nv_bfloat16 hi = __float2bfloat16(w);
    g_Whi[i] = hi;
    g_Wlo[i] = __float2bfloat16(w - __bfloat162float(hi));
}

// ---------------- K2b: fold bias into BN scale/shift (proven) ---------------
__global__ void prep_params(
    const void* __restrict__ eidx, const float* __restrict__ eb,
    const float* __restrict__ bnw, const float* __restrict__ bnb,
    const float* __restrict__ rm, const float* __restrict__ rv)
{
    int i = blockIdx.x * 1024 + threadIdx.x;
    int e = i >> 10, h = i & 1023;
    int se = load_expert_idx(eidx, e);
    size_t s = (size_t)se * HID + h;
    float inv = rsqrtf(rv[s] + EPSBN);
    float sc  = bnw[s] * inv;
    float sh  = fmaf(-rm[s], sc, bnb[s]);
    g_scale[i] = sc;
    g_shift[i] = fmaf(eb[s], sc, sh);
}

// ---------------- K3: fused GEMM, 4-stage cp.async, single sync/iter --------
#define SWZ(o)   ((o) ^ (((o) >> 3) & 0x70))   /* SW128: 128B rows (B tiles) */
#define SWZ64(o) ((o) ^ (((o) >> 3) & 0x30))   /* SW64:  64B rows (A tiles) */

__device__ __forceinline__ uint32_t smem_u32(const void* p) {
    return (uint32_t)__cvta_generic_to_shared(p);
}
__device__ __forceinline__ void ldsm_x4(uint32_t* r, uint32_t a) {
    asm volatile("ldmatrix.sync.aligned.m8n8.x4.shared.b16 {%0,%1,%2,%3}, [%4];"
                 : "=r"(r[0]), "=r"(r[1]), "=r"(r[2]), "=r"(r[3]) : "r"(a));
}
__device__ __forceinline__ void ldsm_x4_t(uint32_t* r, uint32_t a) {
    asm volatile("ldmatrix.sync.aligned.m8n8.x4.trans.shared.b16 {%0,%1,%2,%3}, [%4];"
                 : "=r"(r[0]), "=r"(r[1]), "=r"(r[2]), "=r"(r[3]) : "r"(a));
}
__device__ __forceinline__ void mma16816(float* c, const uint32_t* a, const uint32_t* b) {
    asm volatile(
        "mma.sync.aligned.m16n8k16.row.col.f32.bf16.bf16.f32 "
        "{%0,%1,%2,%3}, {%4,%5,%6,%7}, {%8,%9}, {%0,%1,%2,%3};"
        : "+f"(c[0]), "+f"(c[1]), "+f"(c[2]), "+f"(c[3])
        : "r"(a[0]), "r"(a[1]), "r"(a[2]), "r"(a[3]), "r"(b[0]), "r"(b[1]));
}
#define CP16(d, s)  asm volatile("cp.async.cg.shared.global [%0], [%1], 16;" :: "r"(d), "l"(s) : "memory")
#define CP_COMMIT() asm volatile("cp.async.commit_group;" ::: "memory")
#define CP_WAIT2()  asm volatile("cp.async.wait_group 2;" ::: "memory")

// issue loads for flat iteration t (e = t>>4, kc = t&15) into given stage base
__device__ __forceinline__ void load_stage(uint32_t base, int bblk, int hblk,
                                           int t, int tid)
{
    const int e = t >> 4, kc = t & 15;
    // A: 128 rows x 32 k bf16 (64B rows, SW64), hi + lo (8KB each)
#pragma unroll
    for (int j = 0; j < 2; j++) {
        int idx = j * 256 + tid;                 // 0..511
        int r = idx >> 2, c = idx & 3;
        size_t go = (size_t)(bblk * 128 + r) * IN_DIM + kc * 32 + c * 8;
        uint32_t d = base + SWZ64(r * 64 + c * 16);
        CP16(d,        g_xg_hi + go);
        CP16(d + 8192, g_xg_lo + go);
    }
    // B: 32 k-rows x 64 n-cols (128B rows, SW128), hi + lo (4KB each)
    {
        int r = tid >> 3, c = tid & 7;           // r: 0..31
        size_t go = ((size_t)e * IN_DIM + kc * 32 + r) * HID + hblk * 64 + c * 8;
        uint32_t d = base + SWZ(r * 128 + c * 16);
        CP16(d + 16384, g_Whi + go);
        CP16(d + 20480, g_Wlo + go);
    }
    CP_COMMIT();
}

__global__ void __launch_bounds__(256, 2) fused_moe(float* __restrict__ out)
{
    extern __shared__ __align__(1024) char smem[];
    const uint32_t sb = smem_u32(smem);

    const int tid  = threadIdx.x;
    const int lane = tid & 31, wid = tid >> 5;
    const int hblk = blockIdx.x, bblk = blockIdx.y;
    const int wm = wid >> 1, wn = wid & 1;
    const int m0 = wm * 32,  n0 = wn * 32;
    const int i8 = lane & 7, g8 = lane >> 3;
    const int tig = lane & 3, grp = lane >> 2;

    float o[2][4][4];
#pragma unroll
    for (int a = 0; a < 2; a++)
#pragma unroll
        for (int b = 0; b < 4; b++)
#pragma unroll
            for (int d = 0; d < 4; d++) o[a][b][d] = 0.f;

    float c[2][4][4];
#pragma unroll
    for (int a = 0; a < 2; a++)
#pragma unroll
        for (int b = 0; b < 4; b++)
#pragma unroll
            for (int d = 0; d < 4; d++) c[a][b][d] = 0.f;

    // prologue: stages 0,1,2
    load_stage(sb + 0 * STAGE_BYTES, bblk, hblk, 0, tid);
    load_stage(sb + 1 * STAGE_BYTES, bblk, hblk, 1, tid);
    load_stage(sb + 2 * STAGE_BYTES, bblk, hblk, 2, tid);

    for (int t = 0; t < NITER; t++) {            // e = t>>4, kc = t&15
        CP_WAIT2();                              // groups {t,t+1,t+2} live -> t done
        __syncthreads();                         // all readers of buf[(t-1)&3] done

        if (t + 3 < NITER)
            load_stage(sb + ((t + 3) & 3) * STAGE_BYTES, bblk, hblk, t + 3, tid);
        else
            CP_COMMIT();                         // empty group keeps accounting exact

        const uint32_t base = sb + (t & 3) * STAGE_BYTES;
        const uint32_t uAhi = base, uAlo = base + 8192;
        const uint32_t uBhi = base + 16384, uBlo = base + 20480;

#pragma unroll
        for (int ks = 0; ks < 2; ks++) {
            const int k0 = ks * 16;
            uint32_t ah[2][4], al[2][4];
#pragma unroll
            for (int mt = 0; mt < 2; mt++) {
                int row = m0 + mt * 16 + i8 + ((g8 & 1) << 3);
                int col = k0 + ((g8 >> 1) << 3);
                uint32_t d = SWZ64(row * 64 + col * 2);
                ldsm_x4(ah[mt], uAhi + d);
                ldsm_x4(al[mt], uAlo + d);
            }
            uint32_t bh[4][2], bl[4][2];
#pragma unroll
            for (int q = 0; q < 2; q++) {
                int row = k0 + ((g8 & 1) << 3) + i8;
                int col = n0 + q * 16 + ((g8 >> 1) << 3);
                uint32_t d = SWZ(row * 128 + col * 2);
                uint32_t tt[4];
                ldsm_x4_t(tt, uBhi + d);
                bh[q * 2][0] = tt[0]; bh[q * 2][1] = tt[1];
                bh[q * 2 + 1][0] = tt[2]; bh[q * 2 + 1][1] = tt[3];
                ldsm_x4_t(tt, uBlo + d);
                bl[q * 2][0] = tt[0]; bl[q * 2][1] = tt[1];
                bl[q * 2 + 1][0] = tt[2]; bl[q * 2 + 1][1] = tt[3];
            }
#pragma unroll
            for (int mt = 0; mt < 2; mt++)
#pragma unroll
                for (int ng = 0; ng < 4; ng++) {
                    mma16816(c[mt][ng], ah[mt], bh[ng]);   // hi*hi
                    mma16816(c[mt][ng], ah[mt], bl[ng]);   // hi*lo
                    mma16816(c[mt][ng], al[mt], bh[ng]);   // lo*hi
                }
        }

        if ((t & 15) == 15) {
            // -------- per-expert epilogue: BN + SiLU + gated accumulate ------
            const int e = t >> 4;
            const float* scp = g_scale + e * HID + hblk * 64;
            const float* shp = g_shift + e * HID + hblk * 64;
#pragma unroll
            for (int mt = 0; mt < 2; mt++) {
                int b0 = bblk * 128 + m0 + mt * 16 + grp;
                float gw0 = __ldg(&g_gate[b0 * 16 + e]);
                float gw1 = __ldg(&g_gate[(b0 + 8) * 16 + e]);
#pragma unroll
                for (int ng = 0; ng < 4; ng++) {
                    int hl = n0 + ng * 8 + tig * 2;
                    float sc0 = __ldg(scp + hl), sc1 = __ldg(scp + hl + 1);
                    float sh0 = __ldg(shp + hl), sh1 = __ldg(shp + hl + 1);
                    float z;
                    z = fmaf(c[mt][ng][0], sc0, sh0);
                    o[mt][ng][0] = fmaf(gw0, __fdividef(z, 1.f + __expf(-z)), o[mt][ng][0]);
                    z = fmaf(c[mt][ng][1], sc1, sh1);
                    o[mt][ng][1] = fmaf(gw0, __fdividef(z, 1.f + __expf(-z)), o[mt][ng][1]);
                    z = fmaf(c[mt][ng][2], sc0, sh0);
                    o[mt][ng][2] = fmaf(gw1, __fdividef(z, 1.f + __expf(-z)), o[mt][ng][2]);
                    z = fmaf(c[mt][ng][3], sc1, sh1);
                    o[mt][ng][3] = fmaf(gw1, __fdividef(z, 1.f + __expf(-z)), o[mt][ng][3]);
                    c[mt][ng][0] = 0.f; c[mt][ng][1] = 0.f;
                    c[mt][ng][2] = 0.f; c[mt][ng][3] = 0.f;
                }
            }
        }
    }

    // -------- store combined output --------
#pragma unroll
    for (int mt = 0; mt < 2; mt++) {
        int b0 = bblk * 128 + m0 + mt * 16 + grp;
#pragma unroll
        for (int ng = 0; ng < 4; ng++) {
            int h = hblk * 64 + n0 + ng * 8 + tig * 2;
            *(float2*)(out + (size_t)b0 * HID + h)       = make_float2(o[mt][ng][0], o[mt][ng][1]);
            *(float2*)(out + (size_t)(b0 + 8) * HID + h) = make_float2(o[mt][ng][2], o[mt][ng][3]);
        }
    }
}

// ---------------- launch ------------------------------------------------------
extern "C" void kernel_launch(void* const* d_in, const int* in_sizes, int n_in,
                              void* d_out, int out_size)
{
    const float* x   = (const float*)d_in[0];
    const float* gs  = (const float*)d_in[1];
    const void*  ei  = d_in[2];
    const float* ew  = (const float*)d_in[3];
    const float* eb  = (const float*)d_in[4];
    const float* bnw = (const float*)d_in[5];
    const float* bnb = (const float*)d_in[6];
    const float* rm  = (const float*)d_in[7];
    const float* rv  = (const float*)d_in[8];
    const float* gw  = (const float*)d_in[9];
    const float* lA  = (const float*)d_in[10];
    const float* lB  = (const float*)d_in[11];
    float* out = (float*)d_out;

    cudaFuncSetAttribute(fused_moe, cudaFuncAttributeMaxDynamicSharedMemorySize, SMEM_TOTAL);

    prep_xg_gate<<<BATCH, 128>>>(x, gs, gw, lA, lB);
    prep_W<<<(NEXP * IN_DIM * HID) / 256, 256>>>(ei, ew);
    prep_params<<<16, 1024>>>(ei, eb, bnw, bnb, rm, rv);
    fused_moe<<<dim3(HID / 64, BATCH / 128), 256, SMEM_TOTAL>>>(out);
}

// round 7
// speedup vs baseline: 1.1207x; 1.1207x over previous
#include <cuda_runtime.h>
#include <cuda_bf16.h>
#include <cstdint>

#define BATCH   2048
#define IN_DIM  512
#define HID     1024
#define NEXP    16
#define EPSBN   1e-5f

// dynamic smem: 2 stages x 48KB.  stage layout: Ahi 16K | Alo 16K | Bhi 8K | Blo 8K
#define STAGE_BYTES 49152
#define SMEM_TOTAL  (2 * STAGE_BYTES)

// ---------------- scratch (device globals) -----------------------------------
__device__ __align__(1024) __nv_bfloat16 g_xg_hi[BATCH * IN_DIM];
__device__ __align__(1024) __nv_bfloat16 g_xg_lo[BATCH * IN_DIM];
__device__ __align__(1024) __nv_bfloat16 g_Whi[NEXP * IN_DIM * HID];   // [e][k][n]
__device__ __align__(1024) __nv_bfloat16 g_Wlo[NEXP * IN_DIM * HID];
__device__ float g_gate[BATCH * NEXP];
__device__ float g_scale[NEXP * HID];
__device__ float g_shift[NEXP * HID];

// int32/int64-agnostic expert index decode (validated round 2)
__device__ __forceinline__ int load_expert_idx(const void* p, int e) {
    const int* v = (const int*)p;
    bool is64 = ((v[1] | v[3] | v[5] | v[7]) == 0);
    return (is64 ? v[2 * e] : v[e]) & (NEXP - 1);
}

// ---------------- K1: LoRA sigmoid gate + softmax gate (proven) -------------
__global__ void __launch_bounds__(128) prep_xg_gate(
    const float* __restrict__ x, const float* __restrict__ gs_in,
    const float* __restrict__ gate_w, const float* __restrict__ lora_A,
    const float* __restrict__ lora_B)
{
    int row = blockIdx.x, tid = threadIdx.x, lane = tid & 31, wid = tid >> 5;
    __shared__ float xs[IN_DIM], gss[IN_DIM], w0s[4], w1s[4], pesh[4][16];
    for (int i = tid; i < IN_DIM; i += 128) {
        xs[i]  = x[row * IN_DIM + i];
        gss[i] = gs_in[row * IN_DIM + i];
    }
    __syncthreads();
    float p0 = 0.f, p1 = 0.f;
    for (int i = tid; i < IN_DIM; i += 128) {
        float v = xs[i];
        p0 = fmaf(v, lora_A[i * 2 + 0], p0);
        p1 = fmaf(v, lora_A[i * 2 + 1], p1);
    }
#pragma unroll
    for (int o = 16; o > 0; o >>= 1) {
        p0 += __shfl_xor_sync(~0u, p0, o);
        p1 += __shfl_xor_sync(~0u, p1, o);
    }
    if (lane == 0) { w0s[wid] = p0; w1s[wid] = p1; }
    float pe[16];
#pragma unroll
    for (int e = 0; e < 16; e++) pe[e] = 0.f;
    for (int i = tid; i < IN_DIM; i += 128) {
        float v = gss[i];
#pragma unroll
        for (int e = 0; e < 16; e++) pe[e] = fmaf(v, gate_w[i * 16 + e], pe[e]);
    }
#pragma unroll
    for (int o = 16; o > 0; o >>= 1)
#pragma unroll
        for (int e = 0; e < 16; e++) pe[e] += __shfl_xor_sync(~0u, pe[e], o);
    if (lane == 0)
#pragma unroll
        for (int e = 0; e < 16; e++) pesh[wid][e] = pe[e];
    __syncthreads();
    if (tid < 16) {
        float l = pesh[0][tid] + pesh[1][tid] + pesh[2][tid] + pesh[3][tid], m = l;
#pragma unroll
        for (int o = 8; o > 0; o >>= 1) m = fmaxf(m, __shfl_xor_sync(0xffffu, m, o));
        float ex = __expf(l - m), s = ex;
#pragma unroll
        for (int o = 8; o > 0; o >>= 1) s += __shfl_xor_sync(0xffffu, s, o);
        g_gate[row * 16 + tid] = ex / s;
    }
    float t0 = w0s[0] + w0s[1] + w0s[2] + w0s[3];
    float t1 = w1s[0] + w1s[1] + w1s[2] + w1s[3];
    for (int i = tid; i < IN_DIM; i += 128) {
        float z = fmaf(t0, lora_B[i], t1 * lora_B[IN_DIM + i]);
        float v = xs[i] / (1.f + __expf(-z));
        __nv_bfloat16 hi = __float2bfloat16(v);
        g_xg_hi[row * IN_DIM + i] = hi;
        g_xg_lo[row * IN_DIM + i] = __float2bfloat16(v - __bfloat162float(hi));
    }
}

// ---------------- K2: gather + split W, vectorized 8 elems/thread -----------
__global__ void __launch_bounds__(256) prep_W(
    const void* __restrict__ eidx, const float* __restrict__ ew)
{
    int i   = (blockIdx.x * 256 + threadIdx.x) * 8;   // element index
    int e   = i >> 19;                                 // 512*1024 = 2^19
    int rem = i & ((1 << 19) - 1);
    int se  = load_expert_idx(eidx, e);
    const float4* src = (const float4*)(ew + (size_t)se * (IN_DIM * HID) + rem);
    float4 a = src[0], b = src[1];
    float v[8] = {a.x, a.y, a.z, a.w, b.x, b.y, b.z, b.w};
    __nv_bfloat16 hi[8], lo[8];
#pragma unroll
    for (int j = 0; j < 8; j++) {
        hi[j] = __float2bfloat16(v[j]);
        lo[j] = __float2bfloat16(v[j] - __bfloat162float(hi[j]));
    }
    *(uint4*)(g_Whi + i) = *(uint4*)hi;
    *(uint4*)(g_Wlo + i) = *(uint4*)lo;
}

// ---------------- K2b: fold bias into BN scale/shift (proven) ---------------
__global__ void prep_params(
    const void* __restrict__ eidx, const float* __restrict__ eb,
    const float* __restrict__ bnw, const float* __restrict__ bnb,
    const float* __restrict__ rm, const float* __restrict__ rv)
{
    int i = blockIdx.x * 1024 + threadIdx.x;
    int e = i >> 10, h = i & 1023;
    int se = load_expert_idx(eidx, e);
    size_t s = (size_t)se * HID + h;
    float inv = rsqrtf(rv[s] + EPSBN);
    float sc  = bnw[s] * inv;
    float sh  = fmaf(-rm[s], sc, bnb[s]);
    g_scale[i] = sc;
    g_shift[i] = fmaf(eb[s], sc, sh);
}

// ---------------- K3: fused GEMM, 2-stage cp.async, ONE sync/iter -----------
#define SWZ(o) ((o) ^ (((o) >> 3) & 0x70))

__device__ __forceinline__ uint32_t smem_u32(const void* p) {
    return (uint32_t)__cvta_generic_to_shared(p);
}
__device__ __forceinline__ void ldsm_x4(uint32_t* r, uint32_t a) {
    asm volatile("ldmatrix.sync.aligned.m8n8.x4.shared.b16 {%0,%1,%2,%3}, [%4];"
                 : "=r"(r[0]), "=r"(r[1]), "=r"(r[2]), "=r"(r[3]) : "r"(a));
}
__device__ __forceinline__ void ldsm_x4_t(uint32_t* r, uint32_t a) {
    asm volatile("ldmatrix.sync.aligned.m8n8.x4.trans.shared.b16 {%0,%1,%2,%3}, [%4];"
                 : "=r"(r[0]), "=r"(r[1]), "=r"(r[2]), "=r"(r[3]) : "r"(a));
}
__device__ __forceinline__ void mma16816(float* c, const uint32_t* a, const uint32_t* b) {
    asm volatile(
        "mma.sync.aligned.m16n8k16.row.col.f32.bf16.bf16.f32 "
        "{%0,%1,%2,%3}, {%4,%5,%6,%7}, {%8,%9}, {%0,%1,%2,%3};"
        : "+f"(c[0]), "+f"(c[1]), "+f"(c[2]), "+f"(c[3])
        : "r"(a[0]), "r"(a[1]), "r"(a[2]), "r"(a[3]), "r"(b[0]), "r"(b[1]));
}
#define CP16(d, s)  asm volatile("cp.async.cg.shared.global [%0], [%1], 16;" :: "r"(d), "l"(s) : "memory")
#define CP_COMMIT() asm volatile("cp.async.commit_group;" ::: "memory")
#define CP_WAIT0()  asm volatile("cp.async.wait_group 0;" ::: "memory")

// issue one stage of loads for flat iteration t (e = t>>3, kc = t&7)
__device__ __forceinline__ void load_stage(uint32_t base, int bblk, int hblk,
                                           int t, int tid)
{
    const int e = t >> 3, kc = t & 7;
    // A: 128 rows x 64 cols bf16, hi + lo (16KB each)
#pragma unroll
    for (int j = 0; j < 4; j++) {
        int idx = j * 256 + tid;                 // 0..1023
        int r = idx >> 3, c = idx & 7;
        size_t go = (size_t)(bblk * 128 + r) * IN_DIM + kc * 64 + c * 8;
        uint32_t d = base + SWZ(r * 128 + c * 16);
        CP16(d,         g_xg_hi + go);
        CP16(d + 16384, g_xg_lo + go);
    }
    // B: 64 k-rows x 64 n-cols, hi + lo (8KB each)
#pragma unroll
    for (int j = 0; j < 2; j++) {
        int idx = j * 256 + tid;                 // 0..511
        int r = idx >> 3, c = idx & 7;
        size_t go = ((size_t)e * IN_DIM + kc * 64 + r) * HID + hblk * 64 + c * 8;
        uint32_t d = base + SWZ(r * 128 + c * 16);
        CP16(d + 32768, g_Whi + go);
        CP16(d + 40960, g_Wlo + go);
    }
    CP_COMMIT();
}

__global__ void __launch_bounds__(256, 2) fused_moe(float* __restrict__ out)
{
    extern __shared__ __align__(1024) char smem[];
    const uint32_t sb = smem_u32(smem);

    const int tid  = threadIdx.x;
    const int lane = tid & 31, wid = tid >> 5;
    const int hblk = blockIdx.x, bblk = blockIdx.y;
    const int wm = wid >> 1, wn = wid & 1;
    const int m0 = wm * 32,  n0 = wn * 32;
    const int i8 = lane & 7, g8 = lane >> 3;
    const int tig = lane & 3, grp = lane >> 2;

    float o[2][4][4];
#pragma unroll
    for (int a = 0; a < 2; a++)
#pragma unroll
        for (int b = 0; b < 4; b++)
#pragma unroll
            for (int d = 0; d < 4; d++) o[a][b][d] = 0.f;

    float c[2][4][4];
#pragma unroll
    for (int a = 0; a < 2; a++)
#pragma unroll
        for (int b = 0; b < 4; b++)
#pragma unroll
            for (int d = 0; d < 4; d++) c[a][b][d] = 0.f;

    load_stage(sb, bblk, hblk, 0, tid);          // prologue: stage 0

    for (int t = 0; t < 128; t++) {              // e = t>>3, kc = t&7
        CP_WAIT0();                              // stage t landed
        __syncthreads();                         // visible to all; prior reads done

        if (t < 127)                             // overlap with compute(t) below
            load_stage(sb + ((t + 1) & 1) * STAGE_BYTES, bblk, hblk, t + 1, tid);

        const uint32_t base = sb + (t & 1) * STAGE_BYTES;
        const uint32_t uAhi = base, uAlo = base + 16384;
        const uint32_t uBhi = base + 32768, uBlo = base + 40960;

#pragma unroll
        for (int ks = 0; ks < 4; ks++) {
            const int k0 = ks * 16;
            uint32_t ah[2][4], al[2][4];
#pragma unroll
            for (int mt = 0; mt < 2; mt++) {
                int row = m0 + mt * 16 + i8 + ((g8 & 1) << 3);
                int col = k0 + ((g8 >> 1) << 3);
                uint32_t d = SWZ(row * 128 + col * 2);
                ldsm_x4(ah[mt], uAhi + d);
                ldsm_x4(al[mt], uAlo + d);
            }
            uint32_t bh[4][2], bl[4][2];
#pragma unroll
            for (int q = 0; q < 2; q++) {
                int row = k0 + ((g8 & 1) << 3) + i8;
                int col = n0 + q * 16 + ((g8 >> 1) << 3);
                uint32_t d = SWZ(row * 128 + col * 2);
                uint32_t tt[4];
                ldsm_x4_t(tt, uBhi + d);
                bh[q * 2][0] = tt[0]; bh[q * 2][1] = tt[1];
                bh[q * 2 + 1][0] = tt[2]; bh[q * 2 + 1][1] = tt[3];
                ldsm_x4_t(tt, uBlo + d);
                bl[q * 2][0] = tt[0]; bl[q * 2][1] = tt[1];
                bl[q * 2 + 1][0] = tt[2]; bl[q * 2 + 1][1] = tt[3];
            }
#pragma unroll
            for (int mt = 0; mt < 2; mt++)
#pragma unroll
                for (int ng = 0; ng < 4; ng++) {
                    mma16816(c[mt][ng], ah[mt], bh[ng]);   // hi*hi
                    mma16816(c[mt][ng], ah[mt], bl[ng]);   // hi*lo
                    mma16816(c[mt][ng], al[mt], bh[ng]);   // lo*hi
                }
        }

        if ((t & 7) == 7) {
            // -------- per-expert epilogue: BN + SiLU + gated accumulate ------
            const int e = t >> 3;
            const float* scp = g_scale + e * HID + hblk * 64;
            const float* shp = g_shift + e * HID + hblk * 64;
#pragma unroll
            for (int mt = 0; mt < 2; mt++) {
                int b0 = bblk * 128 + m0 + mt * 16 + grp;
                float gw0 = __ldg(&g_gate[b0 * 16 + e]);
                float gw1 = __ldg(&g_gate[(b0 + 8) * 16 + e]);
#pragma unroll
                for (int ng = 0; ng < 4; ng++) {
                    int hl = n0 + ng * 8 + tig * 2;
                    float sc0 = __ldg(scp + hl), sc1 = __ldg(scp + hl + 1);
                    float sh0 = __ldg(shp + hl), sh1 = __ldg(shp + hl + 1);
                    float z;
                    z = fmaf(c[mt][ng][0], sc0, sh0);
                    o[mt][ng][0] = fmaf(gw0, __fdividef(z, 1.f + __expf(-z)), o[mt][ng][0]);
                    z = fmaf(c[mt][ng][1], sc1, sh1);
                    o[mt][ng][1] = fmaf(gw0, __fdividef(z, 1.f + __expf(-z)), o[mt][ng][1]);
                    z = fmaf(c[mt][ng][2], sc0, sh0);
                    o[mt][ng][2] = fmaf(gw1, __fdividef(z, 1.f + __expf(-z)), o[mt][ng][2]);
                    z = fmaf(c[mt][ng][3], sc1, sh1);
                    o[mt][ng][3] = fmaf(gw1, __fdividef(z, 1.f + __expf(-z)), o[mt][ng][3]);
                    c[mt][ng][0] = 0.f; c[mt][ng][1] = 0.f;
                    c[mt][ng][2] = 0.f; c[mt][ng][3] = 0.f;
                }
            }
        }
    }

    // -------- store combined output --------
#pragma unroll
    for (int mt = 0; mt < 2; mt++) {
        int b0 = bblk * 128 + m0 + mt * 16 + grp;
#pragma unroll
        for (int ng = 0; ng < 4; ng++) {
            int h = hblk * 64 + n0 + ng * 8 + tig * 2;
            *(float2*)(out + (size_t)b0 * HID + h)       = make_float2(o[mt][ng][0], o[mt][ng][1]);
            *(float2*)(out + (size_t)(b0 + 8) * HID + h) = make_float2(o[mt][ng][2], o[mt][ng][3]);
        }
    }
}

// ---------------- launch ------------------------------------------------------
extern "C" void kernel_launch(void* const* d_in, const int* in_sizes, int n_in,
                              void* d_out, int out_size)
{
    const float* x   = (const float*)d_in[0];
    const float* gs  = (const float*)d_in[1];
    const void*  ei  = d_in[2];
    const float* ew  = (const float*)d_in[3];
    const float* eb  = (const float*)d_in[4];
    const float* bnw = (const float*)d_in[5];
    const float* bnb = (const float*)d_in[6];
    const float* rm  = (const float*)d_in[7];
    const float* rv  = (const float*)d_in[8];
    const float* gw  = (const float*)d_in[9];
    const float* lA  = (const float*)d_in[10];
    const float* lB  = (const float*)d_in[11];
    float* out = (float*)d_out;

    cudaFuncSetAttribute(fused_moe, cudaFuncAttributeMaxDynamicSharedMemorySize, SMEM_TOTAL);

    prep_xg_gate<<<BATCH, 128>>>(x, gs, gw, lA, lB);
    prep_W<<<(NEXP * IN_DIM * HID) / (256 * 8), 256>>>(ei, ew);
    prep_params<<<16, 1024>>>(ei, eb, bnw, bnb, rm, rv);
    fused_moe<<<dim3(HID / 64, BATCH / 128), 256, SMEM_TOTAL>>>(out);
}

// round 8
// speedup vs baseline: 1.2317x; 1.0991x over previous
#include <cuda_runtime.h>
#include <cuda_bf16.h>
#include <cstdint>

#define BATCH   2048
#define IN_DIM  512
#define HID     1024
#define NEXP    16
#define EPSBN   1e-5f

// dynamic smem: 2 stages x 48KB.  stage layout: Ahi 16K | Alo 16K | Bhi 8K | Blo 8K
#define STAGE_BYTES 49152
#define SMEM_TOTAL  (2 * STAGE_BYTES)

// ---------------- scratch (device globals) -----------------------------------
__device__ __align__(1024) __nv_bfloat16 g_xg_hi[BATCH * IN_DIM];
__device__ __align__(1024) __nv_bfloat16 g_xg_lo[BATCH * IN_DIM];
__device__ __align__(1024) __nv_bfloat16 g_Whi[NEXP * IN_DIM * HID];   // [e][k][n]
__device__ __align__(1024) __nv_bfloat16 g_Wlo[NEXP * IN_DIM * HID];
__device__ float g_gate[BATCH * NEXP];
__device__ float g_scale[NEXP * HID];
__device__ float g_shift[NEXP * HID];

// int32/int64-agnostic expert index decode (validated round 2)
__device__ __forceinline__ int load_expert_idx(const void* p, int e) {
    const int* v = (const int*)p;
    bool is64 = ((v[1] | v[3] | v[5] | v[7]) == 0);
    return (is64 ? v[2 * e] : v[e]) & (NEXP - 1);
}

// ---------------- K1: LoRA gate + softmax gate — warp-per-row, no barriers --
__global__ void __launch_bounds__(512) prep_xg_gate(
    const float* __restrict__ x, const float* __restrict__ gs_in,
    const float* __restrict__ gate_w, const float* __restrict__ lora_A,
    const float* __restrict__ lora_B)
{
    const int lane = threadIdx.x & 31, wid = threadIdx.x >> 5;
    const int row = blockIdx.x * 16 + wid;

    const float* xr = x     + (size_t)row * IN_DIM;
    const float* gr = gs_in + (size_t)row * IN_DIM;

    float xv[16], gv[16];
#pragma unroll
    for (int j = 0; j < 16; j++) {
        xv[j] = xr[lane + 32 * j];
        gv[j] = gr[lane + 32 * j];
    }

    // LoRA: t = x @ lora_A   (lora_A [512,2] rank-contiguous)
    float p0 = 0.f, p1 = 0.f;
#pragma unroll
    for (int j = 0; j < 16; j++) {
        int i = lane + 32 * j;
        float2 a = *(const float2*)(lora_A + 2 * i);
        p0 = fmaf(xv[j], a.x, p0);
        p1 = fmaf(xv[j], a.y, p1);
    }
#pragma unroll
    for (int o = 16; o > 0; o >>= 1) {
        p0 += __shfl_xor_sync(~0u, p0, o);
        p1 += __shfl_xor_sync(~0u, p1, o);
    }

    // gate logits: gs_row @ gate_weights  ([512,16] expert-contiguous)
    float pe[16];
#pragma unroll
    for (int e = 0; e < 16; e++) pe[e] = 0.f;
#pragma unroll
    for (int j = 0; j < 16; j++) {
        int i = lane + 32 * j;
        const float4* gwv = (const float4*)(gate_w + (size_t)i * 16);
        float4 w0 = gwv[0], w1 = gwv[1], w2 = gwv[2], w3 = gwv[3];
        float v = gv[j];
        pe[0]  = fmaf(v, w0.x, pe[0]);  pe[1]  = fmaf(v, w0.y, pe[1]);
        pe[2]  = fmaf(v, w0.z, pe[2]);  pe[3]  = fmaf(v, w0.w, pe[3]);
        pe[4]  = fmaf(v, w1.x, pe[4]);  pe[5]  = fmaf(v, w1.y, pe[5]);
        pe[6]  = fmaf(v, w1.z, pe[6]);  pe[7]  = fmaf(v, w1.w, pe[7]);
        pe[8]  = fmaf(v, w2.x, pe[8]);  pe[9]  = fmaf(v, w2.y, pe[9]);
        pe[10] = fmaf(v, w2.z, pe[10]); pe[11] = fmaf(v, w2.w, pe[11]);
        pe[12] = fmaf(v, w3.x, pe[12]); pe[13] = fmaf(v, w3.y, pe[13]);
        pe[14] = fmaf(v, w3.z, pe[14]); pe[15] = fmaf(v, w3.w, pe[15]);
    }
#pragma unroll
    for (int o = 16; o > 0; o >>= 1)
#pragma unroll
        for (int e = 0; e < 16; e++)
            pe[e] += __shfl_xor_sync(~0u, pe[e], o);

    // softmax: every lane holds all 16 logits in registers
    float m = pe[0];
#pragma unroll
    for (int e = 1; e < 16; e++) m = fmaxf(m, pe[e]);
    float ex[16], s = 0.f;
#pragma unroll
    for (int e = 0; e < 16; e++) { ex[e] = __expf(pe[e] - m); s += ex[e]; }
    float inv = __fdividef(1.f, s);
    if (lane < 16) {
        float g = 0.f;
#pragma unroll
        for (int e = 0; e < 16; e++) if (lane == e) g = ex[e];
        g_gate[row * 16 + lane] = g * inv;
    }

    // xg = x * sigmoid(t @ lora_B), bf16 hi/lo split
#pragma unroll
    for (int j = 0; j < 16; j++) {
        int i = lane + 32 * j;
        float z  = fmaf(p0, lora_B[i], p1 * lora_B[IN_DIM + i]);
        float v  = xv[j] * __fdividef(1.f, 1.f + __expf(-z));
        __nv_bfloat16 hi = __float2bfloat16(v);
        g_xg_hi[(size_t)row * IN_DIM + i] = hi;
        g_xg_lo[(size_t)row * IN_DIM + i] = __float2bfloat16(v - __bfloat162float(hi));
    }
}

// ---------------- K2: gather + split W, vectorized 8 elems/thread -----------
__global__ void __launch_bounds__(256) prep_W(
    const void* __restrict__ eidx, const float* __restrict__ ew)
{
    int i   = (blockIdx.x * 256 + threadIdx.x) * 8;
    int e   = i >> 19;
    int rem = i & ((1 << 19) - 1);
    int se  = load_expert_idx(eidx, e);
    const float4* src = (const float4*)(ew + (size_t)se * (IN_DIM * HID) + rem);
    float4 a = src[0], b = src[1];
    float v[8] = {a.x, a.y, a.z, a.w, b.x, b.y, b.z, b.w};
    __nv_bfloat16 hi[8], lo[8];
#pragma unroll
    for (int j = 0; j < 8; j++) {
        hi[j] = __float2bfloat16(v[j]);
        lo[j] = __float2bfloat16(v[j] - __bfloat162float(hi[j]));
    }
    *(uint4*)(g_Whi + i) = *(uint4*)hi;
    *(uint4*)(g_Wlo + i) = *(uint4*)lo;
}

// ---------------- K2b: fold bias into BN scale/shift (proven) ---------------
__global__ void prep_params(
    const void* __restrict__ eidx, const float* __restrict__ eb,
    const float* __restrict__ bnw, const float* __restrict__ bnb,
    const float* __restrict__ rm, const float* __restrict__ rv)
{
    int i = blockIdx.x * 1024 + threadIdx.x;
    int e = i >> 10, h = i & 1023;
    int se = load_expert_idx(eidx, e);
    size_t s = (size_t)se * HID + h;
    float inv = rsqrtf(rv[s] + EPSBN);
    float sc  = bnw[s] * inv;
    float sh  = fmaf(-rm[s], sc, bnb[s]);
    g_scale[i] = sc;
    g_shift[i] = fmaf(eb[s], sc, sh);
}

// ---------------- K3: fused GEMM (round-5 measured-best structure) ----------
#define SWZ(o) ((o) ^ (((o) >> 3) & 0x70))

__device__ __forceinline__ uint32_t smem_u32(const void* p) {
    return (uint32_t)__cvta_generic_to_shared(p);
}
__device__ __forceinline__ void ldsm_x4(uint32_t* r, uint32_t a) {
    asm volatile("ldmatrix.sync.aligned.m8n8.x4.shared.b16 {%0,%1,%2,%3}, [%4];"
                 : "=r"(r[0]), "=r"(r[1]), "=r"(r[2]), "=r"(r[3]) : "r"(a));
}
__device__ __forceinline__ void ldsm_x4_t(uint32_t* r, uint32_t a) {
    asm volatile("ldmatrix.sync.aligned.m8n8.x4.trans.shared.b16 {%0,%1,%2,%3}, [%4];"
                 : "=r"(r[0]), "=r"(r[1]), "=r"(r[2]), "=r"(r[3]) : "r"(a));
}
__device__ __forceinline__ void mma16816(float* c, const uint32_t* a, const uint32_t* b) {
    asm volatile(
        "mma.sync.aligned.m16n8k16.row.col.f32.bf16.bf16.f32 "
        "{%0,%1,%2,%3}, {%4,%5,%6,%7}, {%8,%9}, {%0,%1,%2,%3};"
        : "+f"(c[0]), "+f"(c[1]), "+f"(c[2]), "+f"(c[3])
        : "r"(a[0]), "r"(a[1]), "r"(a[2]), "r"(a[3]), "r"(b[0]), "r"(b[1]));
}
#define CP16(d, s)  asm volatile("cp.async.cg.shared.global [%0], [%1], 16;" :: "r"(d), "l"(s) : "memory")
#define CP_COMMIT() asm volatile("cp.async.commit_group;" ::: "memory")
#define CP_WAIT1()  asm volatile("cp.async.wait_group 1;" ::: "memory")
#define CP_WAIT0()  asm volatile("cp.async.wait_group 0;" ::: "memory")

// issue one stage of loads for flat iteration t (e = t>>3, kc = t&7)
__device__ __forceinline__ void load_stage(uint32_t base, int bblk, int hblk,
                                           int t, int tid)
{
    const int e = t >> 3, kc = t & 7;
#pragma unroll
    for (int j = 0; j < 4; j++) {
        int idx = j * 256 + tid;
        int r = idx >> 3, c = idx & 7;
        size_t go = (size_t)(bblk * 128 + r) * IN_DIM + kc * 64 + c * 8;
        uint32_t d = base + SWZ(r * 128 + c * 16);
        CP16(d,         g_xg_hi + go);
        CP16(d + 16384, g_xg_lo + go);
    }
#pragma unroll
    for (int j = 0; j < 2; j++) {
        int idx = j * 256 + tid;
        int r = idx >> 3, c = idx & 7;
        size_t go = ((size_t)e * IN_DIM + kc * 64 + r) * HID + hblk * 64 + c * 8;
        uint32_t d = base + SWZ(r * 128 + c * 16);
        CP16(d + 32768, g_Whi + go);
        CP16(d + 40960, g_Wlo + go);
    }
    CP_COMMIT();
}

__global__ void __launch_bounds__(256, 2) fused_moe(float* __restrict__ out)
{
    extern __shared__ __align__(1024) char smem[];
    const uint32_t sb = smem_u32(smem);

    const int tid  = threadIdx.x;
    const int lane = tid & 31, wid = tid >> 5;
    const int hblk = blockIdx.x, bblk = blockIdx.y;
    const int wm = wid >> 1, wn = wid & 1;
    const int m0 = wm * 32,  n0 = wn * 32;
    const int i8 = lane & 7, g8 = lane >> 3;
    const int tig = lane & 3, grp = lane >> 2;

    float o[2][4][4];
#pragma unroll
    for (int a = 0; a < 2; a++)
#pragma unroll
        for (int b = 0; b < 4; b++)
#pragma unroll
            for (int d = 0; d < 4; d++) o[a][b][d] = 0.f;

    float c[2][4][4];
#pragma unroll
    for (int a = 0; a < 2; a++)
#pragma unroll
        for (int b = 0; b < 4; b++)
#pragma unroll
            for (int d = 0; d < 4; d++) c[a][b][d] = 0.f;

    load_stage(sb, bblk, hblk, 0, tid);          // prologue

    for (int t = 0; t < 128; t++) {              // e = t>>3, kc = t&7
        if (t < 127) {
            load_stage(sb + ((t + 1) & 1) * STAGE_BYTES, bblk, hblk, t + 1, tid);
            CP_WAIT1();                          // stage t complete
        } else {
            CP_WAIT0();
        }
        __syncthreads();                         // stage t visible to all

        const uint32_t base = sb + (t & 1) * STAGE_BYTES;
        const uint32_t uAhi = base, uAlo = base + 16384;
        const uint32_t uBhi = base + 32768, uBlo = base + 40960;

#pragma unroll
        for (int ks = 0; ks < 4; ks++) {
            const int k0 = ks * 16;
            uint32_t ah[2][4], al[2][4];
#pragma unroll
            for (int mt = 0; mt < 2; mt++) {
                int row = m0 + mt * 16 + i8 + ((g8 & 1) << 3);
                int col = k0 + ((g8 >> 1) << 3);
                uint32_t d = SWZ(row * 128 + col * 2);
                ldsm_x4(ah[mt], uAhi + d);
                ldsm_x4(al[mt], uAlo + d);
            }
            uint32_t bh[4][2], bl[4][2];
#pragma unroll
            for (int q = 0; q < 2; q++) {
                int row = k0 + ((g8 & 1) << 3) + i8;
                int col = n0 + q * 16 + ((g8 >> 1) << 3);
                uint32_t d = SWZ(row * 128 + col * 2);
                uint32_t tt[4];
                ldsm_x4_t(tt, uBhi + d);
                bh[q * 2][0] = tt[0]; bh[q * 2][1] = tt[1];
                bh[q * 2 + 1][0] = tt[2]; bh[q * 2 + 1][1] = tt[3];
                ldsm_x4_t(tt, uBlo + d);
                bl[q * 2][0] = tt[0]; bl[q * 2][1] = tt[1];
                bl[q * 2 + 1][0] = tt[2]; bl[q * 2 + 1][1] = tt[3];
            }
#pragma unroll
            for (int mt = 0; mt < 2; mt++)
#pragma unroll
                for (int ng = 0; ng < 4; ng++) {
                    mma16816(c[mt][ng], ah[mt], bh[ng]);   // hi*hi
                    mma16816(c[mt][ng], ah[mt], bl[ng]);   // hi*lo
                    mma16816(c[mt][ng], al[mt], bh[ng]);   // lo*hi
                }
        }

        if ((t & 7) == 7) {
            const int e = t >> 3;
            const float* scp = g_scale + e * HID + hblk * 64;
            const float* shp = g_shift + e * HID + hblk * 64;
#pragma unroll
            for (int mt = 0; mt < 2; mt++) {
                int b0 = bblk * 128 + m0 + mt * 16 + grp;
                float gw0 = __ldg(&g_gate[b0 * 16 + e]);
                float gw1 = __ldg(&g_gate[(b0 + 8) * 16 + e]);
#pragma unroll
                for (int ng = 0; ng < 4; ng++) {
                    int hl = n0 + ng * 8 + tig * 2;
                    float sc0 = __ldg(scp + hl), sc1 = __ldg(scp + hl + 1);
                    float sh0 = __ldg(shp + hl), sh1 = __ldg(shp + hl + 1);
                    float z;
                    z = fmaf(c[mt][ng][0], sc0, sh0);
                    o[mt][ng][0] = fmaf(gw0, __fdividef(z, 1.f + __expf(-z)), o[mt][ng][0]);
                    z = fmaf(c[mt][ng][1], sc1, sh1);
                    o[mt][ng][1] = fmaf(gw0, __fdividef(z, 1.f + __expf(-z)), o[mt][ng][1]);
                    z = fmaf(c[mt][ng][2], sc0, sh0);
                    o[mt][ng][2] = fmaf(gw1, __fdividef(z, 1.f + __expf(-z)), o[mt][ng][2]);
                    z = fmaf(c[mt][ng][3], sc1, sh1);
                    o[mt][ng][3] = fmaf(gw1, __fdividef(z, 1.f + __expf(-z)), o[mt][ng][3]);
                    c[mt][ng][0] = 0.f; c[mt][ng][1] = 0.f;
                    c[mt][ng][2] = 0.f; c[mt][ng][3] = 0.f;
                }
            }
        }
        __syncthreads();      // readers of stage t done before its buffer refills
    }

    // -------- store combined output --------
#pragma unroll
    for (int mt = 0; mt < 2; mt++) {
        int b0 = bblk * 128 + m0 + mt * 16 + grp;
#pragma unroll
        for (int ng = 0; ng < 4; ng++) {
            int h = hblk * 64 + n0 + ng * 8 + tig * 2;
            *(float2*)(out + (size_t)b0 * HID + h)       = make_float2(o[mt][ng][0], o[mt][ng][1]);
            *(float2*)(out + (size_t)(b0 + 8) * HID + h) = make_float2(o[mt][ng][2], o[mt][ng][3]);
        }
    }
}

// ---------------- launch ------------------------------------------------------
extern "C" void kernel_launch(void* const* d_in, const int* in_sizes, int n_in,
                              void* d_out, int out_size)
{
    const float* x   = (const float*)d_in[0];
    const float* gs  = (const float*)d_in[1];
    const void*  ei  = d_in[2];
    const float* ew  = (const float*)d_in[3];
    const float* eb  = (const float*)d_in[4];
    const float* bnw = (const float*)d_in[5];
    const float* bnb = (const float*)d_in[6];
    const float* rm  = (const float*)d_in[7];
    const float* rv  = (const float*)d_in[8];
    const float* gw  = (const float*)d_in[9];
    const float* lA  = (const float*)d_in[10];
    const float* lB  = (const float*)d_in[11];
    float* out = (float*)d_out;

    cudaFuncSetAttribute(fused_moe, cudaFuncAttributeMaxDynamicSharedMemorySize, SMEM_TOTAL);

    prep_xg_gate<<<BATCH / 16, 512>>>(x, gs, gw, lA, lB);
    prep_W<<<(NEXP * IN_DIM * HID) / (256 * 8), 256>>>(ei, ew);
    prep_params<<<16, 1024>>>(ei, eb, bnw, bnb, rm, rv);
    fused_moe<<<dim3(HID / 64, BATCH / 128), 256, SMEM_TOTAL>>>(out);
}